// round 12
// baseline (speedup 1.0000x reference)
#include <cuda_runtime.h>

// Problem shapes (fixed by the dataset)
constexpr int B  = 8;
constexpr int H  = 512, W  = 512;
constexpr int HO = 1024, WO = 1024;
constexpr int FPY = 514;             // padded rows: y coords -1..512
constexpr int FPX = 516;             // padded row stride (514 valid + 2 pad, float4-aligned)
constexpr int TPR = 129;             // fix col-groups per row (129*4 = 516)
constexpr int NPIX = B * HO * WO;    // 8388608 output pixels
constexpr int NQUAD = NPIX / 4;      // 2097152 output quads
constexpr int NFIXT = B * FPY * TPR;

constexpr int SAMPLE_BLOCKS  = 888;  // 6 CTAs/SM, single persistent wave (R4-best)
constexpr int SAMPLE_THREADS = 256;

// Precomputed "fixed" depth map, padded domain. 8*514*516*4 B = 8.49 MB (L2-resident).
__device__ float4 g_fix4[B * FPY * (FPX / 4)];

// ---------------- pass 1: fix map (best-measured R2 form) ----------------
// Load 6 input floats covering columns [px0-2, px0+3] of `row` (0 if OOB).
__device__ __forceinline__ void load_row6(const float* __restrict__ img, int row,
                                          int px0, float v[6]) {
    if ((unsigned)row >= (unsigned)H) {
        v[0] = v[1] = v[2] = v[3] = v[4] = v[5] = 0.0f;
        return;
    }
    const float* rp = img + row * W;
    if (px0 >= 4 && px0 <= 508) {
        float4 a = *(const float4*)(rp + px0 - 4);
        float4 b = *(const float4*)(rp + px0);
        v[0] = a.z; v[1] = a.w;
        v[2] = b.x; v[3] = b.y; v[4] = b.z; v[5] = b.w;
    } else {
#pragma unroll
        for (int i = 0; i < 6; i++) {
            int c = px0 - 2 + i;
            v[i] = ((unsigned)c < (unsigned)W) ? __ldg(rp + c) : 0.0f;
        }
    }
}

// First-valid among 9 offsets, reference order:
// (0,0), (-1,-1),(-1,0),(-1,1),(0,-1),(0,1),(1,-1),(1,0),(1,1)
__global__ void __launch_bounds__(256) fix_kernel(const float* __restrict__ depth) {
    int idx = blockIdx.x * blockDim.x + threadIdx.x;
    if (idx < NFIXT) {
        int b  = idx / (FPY * TPR);
        int r  = idx - b * (FPY * TPR);
        int py = r / TPR;
        int t  = r - py * TPR;
        int px0 = t * 4;
        int y   = py - 1;

        const float* img = depth + b * (H * W);

        float m1[6], r0[6], p1[6];
        load_row6(img, y - 1, px0, m1);
        load_row6(img, y,     px0, r0);
        load_row6(img, y + 1, px0, p1);

        float4 o;
        float* op = &o.x;
#pragma unroll
        for (int j = 0; j < 4; j++) {
            float c[9] = { r0[j + 1],
                           m1[j], m1[j + 1], m1[j + 2],
                           r0[j],            r0[j + 2],
                           p1[j], p1[j + 1], p1[j + 2] };
            float v = 0.0f;
#pragma unroll
            for (int k = 8; k >= 0; k--) {
                if (c[k] != 0.0f) v = c[k];      // first-valid via reverse last-write
            }
            op[j] = v;
        }
        g_fix4[(b * FPY + py) * (FPX / 4) + t] = o;
    }
    // PDL: allow the dependent sample kernel to launch; all our stores above
    // are visible to dependents that execute griddepcontrol.wait.
    asm volatile("griddepcontrol.launch_dependents;");
}

// ---------------- pass 2: sampler (R4-best shape) ----------------
__device__ __forceinline__ void do_quad(int q, float4 ga, float4 gb,
                                        float4* __restrict__ out) {
    int b = q >> 18;                          // quads never span batches (HO*WO = 1<<20)
    const float* fixp = (const float*)g_fix4 + b * (FPY * FPX);
    float gx[4] = {ga.x, ga.z, gb.x, gb.z};
    float gy[4] = {ga.y, ga.w, gb.y, gb.w};
    float v[4];
#pragma unroll
    for (int i = 0; i < 4; i++) {
        // ((g+1)*0.5)*511 == round_fp32(g+1) * 255.5 exactly (×0.5 exact);
        // __float2int_rn = ties-to-even = jnp.round
        float xf = __fmul_rn(__fadd_rn(gx[i], 1.0f), 255.5f);
        float yf = __fmul_rn(__fadd_rn(gy[i], 1.0f), 255.5f);
        int ix = __float2int_rn(xf) + 1;      // padded coords
        int iy = __float2int_rn(yf) + 1;
        bool inb = ((unsigned)ix < 514u) & ((unsigned)iy < 514u);
        v[i] = inb ? __ldg(fixp + iy * FPX + ix) : 0.0f;
    }
    float4 o = {v[0], v[1], v[2], v[3]};
    __stcs(out + q, o);
}

// Grid-stride, 4 px/iteration, depth-1 grid prefetch. Launched with PDL so the
// prologue (index math + first grid loads, map-independent) overlaps the fix
// kernel's tail; griddepcontrol.wait gates the first map gather.
__global__ void __launch_bounds__(SAMPLE_THREADS)
sample_kernel(const float4* __restrict__ grid, float4* __restrict__ out) {
    const int stride = SAMPLE_BLOCKS * SAMPLE_THREADS;
    int q = blockIdx.x * SAMPLE_THREADS + threadIdx.x;
    if (q >= NQUAD) {
        asm volatile("griddepcontrol.wait;" ::: "memory");
        return;
    }

    float4 ga = __ldcs(grid + 2 * q);          // map-independent prologue
    float4 gb = __ldcs(grid + 2 * q + 1);

    asm volatile("griddepcontrol.wait;" ::: "memory");   // fix map now visible

    int qn = q + stride;
    while (qn < NQUAD) {
        float4 na = __ldcs(grid + 2 * qn);     // prefetch next (overlaps gathers)
        float4 nb = __ldcs(grid + 2 * qn + 1);
        do_quad(q, ga, gb, out);
        q = qn; qn += stride;
        ga = na; gb = nb;
    }
    do_quad(q, ga, gb, out);
}

extern "C" void kernel_launch(void* const* d_in, const int* in_sizes, int n_in,
                              void* d_out, int out_size) {
    const float*  depth = (const float*)d_in[0];   // (B,1,H,W) f32
    const float4* grid  = (const float4*)d_in[1];  // (B,Ho,Wo,2) f32 as float4
    float4*       out   = (float4*)d_out;          // (B,1,Ho,Wo) f32 as float4

    fix_kernel<<<(NFIXT + 255) / 256, 256>>>(depth);

    // Sample kernel launches with programmatic stream serialization: it may
    // begin while fix_kernel drains; griddepcontrol.wait provides ordering.
    cudaLaunchConfig_t cfg = {};
    cfg.gridDim  = dim3(SAMPLE_BLOCKS, 1, 1);
    cfg.blockDim = dim3(SAMPLE_THREADS, 1, 1);
    cudaLaunchAttribute attrs[1];
    attrs[0].id = cudaLaunchAttributeProgrammaticStreamSerialization;
    attrs[0].val.programmaticStreamSerializationAllowed = 1;
    cfg.attrs = attrs;
    cfg.numAttrs = 1;
    cudaLaunchKernelEx(&cfg, sample_kernel, grid, out);
}

// round 13
// speedup vs baseline: 1.1098x; 1.1098x over previous
#include <cuda_runtime.h>

// Problem shapes (fixed by the dataset)
constexpr int B  = 8;
constexpr int H  = 512, W  = 512;
constexpr int HO = 1024, WO = 1024;
constexpr int FPY = 514;             // padded rows: y coords -1..512
constexpr int FPX = 516;             // padded row stride (514 valid + 2 pad, float4-aligned)
constexpr int TPR = 129;             // fix col-groups per row (129*4 = 516)
constexpr int NPIX = B * HO * WO;    // 8388608 output pixels
constexpr int NQUAD = NPIX / 4;      // 2097152 output quads
constexpr int NFIXT = B * FPY * TPR;

// 8 CTAs/SM * 148 SMs = 1184 CTAs = exactly one full-occupancy wave
// (2048 threads/SM; 30 regs <= 32-reg cap from __launch_bounds__(256, 8)).
constexpr int SAMPLE_BLOCKS  = 1184;
constexpr int SAMPLE_THREADS = 256;

// Precomputed "fixed" depth map, padded domain. 8*514*516*4 B = 8.49 MB (L2-resident).
__device__ float4 g_fix4[B * FPY * (FPX / 4)];

// ---------------- pass 1: fix map (best-measured R2 form) ----------------
// Load 6 input floats covering columns [px0-2, px0+3] of `row` (0 if OOB).
__device__ __forceinline__ void load_row6(const float* __restrict__ img, int row,
                                          int px0, float v[6]) {
    if ((unsigned)row >= (unsigned)H) {
        v[0] = v[1] = v[2] = v[3] = v[4] = v[5] = 0.0f;
        return;
    }
    const float* rp = img + row * W;
    if (px0 >= 4 && px0 <= 508) {
        float4 a = *(const float4*)(rp + px0 - 4);
        float4 b = *(const float4*)(rp + px0);
        v[0] = a.z; v[1] = a.w;
        v[2] = b.x; v[3] = b.y; v[4] = b.z; v[5] = b.w;
    } else {
#pragma unroll
        for (int i = 0; i < 6; i++) {
            int c = px0 - 2 + i;
            v[i] = ((unsigned)c < (unsigned)W) ? __ldg(rp + c) : 0.0f;
        }
    }
}

// First-valid among 9 offsets, reference order:
// (0,0), (-1,-1),(-1,0),(-1,1),(0,-1),(0,1),(1,-1),(1,0),(1,1)
__global__ void __launch_bounds__(256) fix_kernel(const float* __restrict__ depth) {
    int idx = blockIdx.x * blockDim.x + threadIdx.x;
    if (idx >= NFIXT) return;
    int b  = idx / (FPY * TPR);
    int r  = idx - b * (FPY * TPR);
    int py = r / TPR;
    int t  = r - py * TPR;
    int px0 = t * 4;
    int y   = py - 1;

    const float* img = depth + b * (H * W);

    float m1[6], r0[6], p1[6];
    load_row6(img, y - 1, px0, m1);
    load_row6(img, y,     px0, r0);
    load_row6(img, y + 1, px0, p1);

    float4 o;
    float* op = &o.x;
#pragma unroll
    for (int j = 0; j < 4; j++) {
        float c[9] = { r0[j + 1],
                       m1[j], m1[j + 1], m1[j + 2],
                       r0[j],            r0[j + 2],
                       p1[j], p1[j + 1], p1[j + 2] };
        float v = 0.0f;
#pragma unroll
        for (int k = 8; k >= 0; k--) {
            if (c[k] != 0.0f) v = c[k];      // first-valid via reverse last-write
        }
        op[j] = v;
    }
    g_fix4[(b * FPY + py) * (FPX / 4) + t] = o;
}

// ---------------- pass 2: sampler ----------------
__device__ __forceinline__ void do_quad(int q, float4 ga, float4 gb,
                                        float4* __restrict__ out) {
    int b = q >> 18;                          // quads never span batches (HO*WO = 1<<20)
    const float* fixp = (const float*)g_fix4 + b * (FPY * FPX);
    float gx[4] = {ga.x, ga.z, gb.x, gb.z};
    float gy[4] = {ga.y, ga.w, gb.y, gb.w};
    float v[4];
#pragma unroll
    for (int i = 0; i < 4; i++) {
        // ((g+1)*0.5)*511 == round_fp32(g+1) * 255.5 exactly (×0.5 exact);
        // __float2int_rn = ties-to-even = jnp.round
        float xf = __fmul_rn(__fadd_rn(gx[i], 1.0f), 255.5f);
        float yf = __fmul_rn(__fadd_rn(gy[i], 1.0f), 255.5f);
        int ix = __float2int_rn(xf) + 1;      // padded coords
        int iy = __float2int_rn(yf) + 1;
        bool inb = ((unsigned)ix < 514u) & ((unsigned)iy < 514u);
        v[i] = inb ? __ldg(fixp + iy * FPX + ix) : 0.0f;
    }
    float4 o = {v[0], v[1], v[2], v[3]};
    __stcs(out + q, o);
}

// Grid-stride, 4 px/iteration, depth-1 grid prefetch; 8 CTAs/SM single wave
// at 100% theoretical occupancy (reg cap 32 via __launch_bounds__(256, 8)).
__global__ void __launch_bounds__(SAMPLE_THREADS, 8)
sample_kernel(const float4* __restrict__ grid, float4* __restrict__ out) {
    const int stride = SAMPLE_BLOCKS * SAMPLE_THREADS;
    int q = blockIdx.x * SAMPLE_THREADS + threadIdx.x;
    if (q >= NQUAD) return;

    float4 ga = __ldcs(grid + 2 * q);
    float4 gb = __ldcs(grid + 2 * q + 1);

    int qn = q + stride;
    while (qn < NQUAD) {
        float4 na = __ldcs(grid + 2 * qn);     // prefetch next (overlaps gathers)
        float4 nb = __ldcs(grid + 2 * qn + 1);
        do_quad(q, ga, gb, out);
        q = qn; qn += stride;
        ga = na; gb = nb;
    }
    do_quad(q, ga, gb, out);
}

extern "C" void kernel_launch(void* const* d_in, const int* in_sizes, int n_in,
                              void* d_out, int out_size) {
    const float*  depth = (const float*)d_in[0];   // (B,1,H,W) f32
    const float4* grid  = (const float4*)d_in[1];  // (B,Ho,Wo,2) f32 as float4
    float4*       out   = (float4*)d_out;          // (B,1,Ho,Wo) f32 as float4

    fix_kernel<<<(NFIXT + 255) / 256, 256>>>(depth);
    sample_kernel<<<SAMPLE_BLOCKS, SAMPLE_THREADS>>>(grid, out);
}

// round 14
// speedup vs baseline: 1.1107x; 1.0009x over previous
#include <cuda_runtime.h>

// Problem shapes (fixed by the dataset)
constexpr int B  = 8;
constexpr int H  = 512, W  = 512;
constexpr int HO = 1024, WO = 1024;
constexpr int FPY = 514;             // padded rows: y coords -1..512
constexpr int FPX = 516;             // padded row stride (514 valid + 2 pad, float4-aligned)
constexpr int TPR = 129;             // fix col-groups per row (129*4 = 516)
constexpr int NPIX = B * HO * WO;    // 8388608 output pixels
constexpr int NQUAD = NPIX / 4;      // 2097152 output quads
constexpr int NFIXT = B * FPY * TPR;

// R4-exact sampler shape: 888 CTAs (6/SM single wave), 256 threads, 30 regs.
constexpr int SAMPLE_BLOCKS  = 888;
constexpr int SAMPLE_THREADS = 256;

// Precomputed "fixed" depth map, padded domain. 8*514*516*4 B = 8.49 MB (L2-resident).
__device__ float4 g_fix4[B * FPY * (FPX / 4)];

// ---------------- pass 1: fix map (best-measured flat form) ----------------
// Load 6 input floats covering columns [px0-2, px0+3] of `row` (0 if OOB).
__device__ __forceinline__ void load_row6(const float* __restrict__ img, int row,
                                          int px0, float v[6]) {
    if ((unsigned)row >= (unsigned)H) {
        v[0] = v[1] = v[2] = v[3] = v[4] = v[5] = 0.0f;
        return;
    }
    const float* rp = img + row * W;
    if (px0 >= 4 && px0 <= 508) {
        float4 a = *(const float4*)(rp + px0 - 4);
        float4 b = *(const float4*)(rp + px0);
        v[0] = a.z; v[1] = a.w;
        v[2] = b.x; v[3] = b.y; v[4] = b.z; v[5] = b.w;
    } else {
#pragma unroll
        for (int i = 0; i < 6; i++) {
            int c = px0 - 2 + i;
            v[i] = ((unsigned)c < (unsigned)W) ? __ldg(rp + c) : 0.0f;
        }
    }
}

// First-valid among 9 offsets, reference order:
// (0,0), (-1,-1),(-1,0),(-1,1),(0,-1),(0,1),(1,-1),(1,0),(1,1)
__global__ void __launch_bounds__(256) fix_kernel(const float* __restrict__ depth) {
    int idx = blockIdx.x * blockDim.x + threadIdx.x;
    if (idx >= NFIXT) return;
    int b  = idx / (FPY * TPR);
    int r  = idx - b * (FPY * TPR);
    int py = r / TPR;
    int t  = r - py * TPR;
    int px0 = t * 4;
    int y   = py - 1;

    const float* img = depth + b * (H * W);

    float m1[6], r0[6], p1[6];
    load_row6(img, y - 1, px0, m1);
    load_row6(img, y,     px0, r0);
    load_row6(img, y + 1, px0, p1);

    float4 o;
    float* op = &o.x;
#pragma unroll
    for (int j = 0; j < 4; j++) {
        float c[9] = { r0[j + 1],
                       m1[j], m1[j + 1], m1[j + 2],
                       r0[j],            r0[j + 2],
                       p1[j], p1[j + 1], p1[j + 2] };
        float v = 0.0f;
#pragma unroll
        for (int k = 8; k >= 0; k--) {
            if (c[k] != 0.0f) v = c[k];      // first-valid via reverse last-write
        }
        op[j] = v;
    }
    g_fix4[(b * FPY + py) * (FPX / 4) + t] = o;
}

// ---------------- pass 2: sampler (R4-exact, best measured 31.6us) ----------------
__device__ __forceinline__ void do_quad(int q, float4 ga, float4 gb,
                                        float4* __restrict__ out) {
    int b = q >> 18;                          // quads never span batches (HO*WO = 1<<20)
    const float* fixp = (const float*)g_fix4 + b * (FPY * FPX);
    float gx[4] = {ga.x, ga.z, gb.x, gb.z};
    float gy[4] = {ga.y, ga.w, gb.y, gb.w};
    float v[4];
#pragma unroll
    for (int i = 0; i < 4; i++) {
        // ((g+1)*0.5)*511 == round_fp32(g+1) * 255.5 exactly (×0.5 exact);
        // __float2int_rn = ties-to-even = jnp.round
        float xf = __fmul_rn(__fadd_rn(gx[i], 1.0f), 255.5f);
        float yf = __fmul_rn(__fadd_rn(gy[i], 1.0f), 255.5f);
        int ix = __float2int_rn(xf) + 1;      // padded coords
        int iy = __float2int_rn(yf) + 1;
        bool inb = ((unsigned)ix < 514u) & ((unsigned)iy < 514u);
        v[i] = inb ? __ldg(fixp + iy * FPX + ix) : 0.0f;
    }
    float4 o = {v[0], v[1], v[2], v[3]};
    __stcs(out + q, o);
}

// Grid-stride, 4 px/iteration, next iteration's grid prefetched while the
// current 4 gathers are in flight (proven in-flight depth).
__global__ void __launch_bounds__(SAMPLE_THREADS)
sample_kernel(const float4* __restrict__ grid, float4* __restrict__ out) {
    const int stride = SAMPLE_BLOCKS * SAMPLE_THREADS;
    int q = blockIdx.x * SAMPLE_THREADS + threadIdx.x;
    if (q >= NQUAD) return;

    float4 ga = __ldcs(grid + 2 * q);
    float4 gb = __ldcs(grid + 2 * q + 1);

    int qn = q + stride;
    while (qn < NQUAD) {
        float4 na = __ldcs(grid + 2 * qn);     // prefetch next (overlaps gathers)
        float4 nb = __ldcs(grid + 2 * qn + 1);
        do_quad(q, ga, gb, out);
        q = qn; qn += stride;
        ga = na; gb = nb;
    }
    do_quad(q, ga, gb, out);
}

extern "C" void kernel_launch(void* const* d_in, const int* in_sizes, int n_in,
                              void* d_out, int out_size) {
    const float*  depth = (const float*)d_in[0];   // (B,1,H,W) f32
    const float4* grid  = (const float4*)d_in[1];  // (B,Ho,Wo,2) f32 as float4
    float4*       out   = (float4*)d_out;          // (B,1,Ho,Wo) f32 as float4

    fix_kernel<<<(NFIXT + 255) / 256, 256>>>(depth);
    sample_kernel<<<SAMPLE_BLOCKS, SAMPLE_THREADS>>>(grid, out);
}